// round 13
// baseline (speedup 1.0000x reference)
#include <cuda_runtime.h>
#include <cuda_bf16.h>
#include <cstdint>
#include <math.h>

// ---------------------------------------------------------------------------
// Problem constants
// ---------------------------------------------------------------------------
#define B_  4
#define C_  256
#define CO_ 256
#define H_  64
#define W_  64
#define HW_ 4096
#define K_  9
#define CK_ 2304
#define BN_EPS 1e-5f

// Is the arch-specific (tcgen05-capable) target available for this pass?
#if defined(__CUDA_ARCH_FEAT_SM103_ALL) || defined(__CUDA_ARCH_FEAT_SM100_ALL)
#define HAS_TCGEN05 1
#else
#define HAS_TCGEN05 0
#endif

// ---------------------------------------------------------------------------
// Device scratch (module-scope globals: allocation-free per harness rules)
// ---------------------------------------------------------------------------
__device__ float g_part[4 * B_ * 27 * HW_];
__device__ float g_off [B_ * 18 * HW_];
__device__ float g_mask[B_ * 9 * HW_];
__device__ __align__(256) float g_xT[(size_t)B_ * HW_ * C_];              // x transposed [b][pix][c]
__device__ __align__(256) __nv_bfloat16 g_colh[(size_t)B_ * HW_ * CK_];  // col hi [b][p][k*256+c]
__device__ __align__(256) __nv_bfloat16 g_coll[(size_t)B_ * HW_ * CK_];  // col lo
__device__ __align__(256) __nv_bfloat16 g_wh[CO_ * CK_];                 // w hi   [o][k*256+c]
__device__ __align__(256) __nv_bfloat16 g_wl[CO_ * CK_];                 // w lo

// ---------------------------------------------------------------------------
// Portable PTX helpers (sm_80+ only: cp.async, ldmatrix, mma.sync)
// ---------------------------------------------------------------------------
__device__ __forceinline__ uint32_t smem_to_u32(const void* smem_ptr) {
    uint32_t addr;
    asm("{ .reg .u64 tmp; cvta.to.shared.u64 tmp, %1; cvt.u32.u64 %0, tmp; }"
        : "=r"(addr) : "l"(smem_ptr));
    return addr;
}

#define CPA16(dst, src) \
    asm volatile("cp.async.cg.shared.global [%0], [%1], 16;" \
                 :: "r"((uint32_t)(dst)), "l"(src))
#define CPA_COMMIT()    asm volatile("cp.async.commit_group;" ::: "memory")
#define CPA_WAIT(n)     asm volatile("cp.async.wait_group %0;" :: "n"(n) : "memory")

#define SMEM_SWIZZLE_128B(byte_offset) \
    ((byte_offset) ^ (((byte_offset) >> 3) & 0x70))

#define LDSM_X4(r0, r1, r2, r3, addr) \
    asm volatile("ldmatrix.sync.aligned.m8n8.x4.shared.b16 {%0, %1, %2, %3}, [%4];" \
        : "=r"(r0), "=r"(r1), "=r"(r2), "=r"(r3) : "r"(addr))

#define MMA16816(c, a, b0, b1) \
    asm volatile("mma.sync.aligned.m16n8k16.row.col.f32.bf16.bf16.f32 " \
        "{%0, %1, %2, %3}, {%4, %5, %6, %7}, {%8, %9}, {%0, %1, %2, %3};" \
        : "+f"((c)[0]), "+f"((c)[1]), "+f"((c)[2]), "+f"((c)[3]) \
        : "r"((a)[0]), "r"((a)[1]), "r"((a)[2]), "r"((a)[3]), "r"(b0), "r"(b1))

// ---------------------------------------------------------------------------
// a-gated helpers (ONLY expanded inside HAS_TCGEN05 regions)
// ---------------------------------------------------------------------------
__device__ __forceinline__ uint32_t elect_one_pred() {
    uint32_t pred;
    asm volatile(
        "{\n\t.reg .pred p;\n\telect.sync _|p, 0xFFFFFFFF;\n\tselp.b32 %0, 1, 0, p;\n\t}"
        : "=r"(pred));
    return pred;
}

#define MBARRIER_INIT(mbar, count) \
    asm volatile("mbarrier.init.shared.b64 [%0], %1;" \
                 :: "r"((uint32_t)(mbar)), "r"((uint32_t)(count)) : "memory")
#define MBARRIER_INVAL(mbar) \
    asm volatile("mbarrier.inval.shared.b64 [%0];" :: "r"((uint32_t)(mbar)) : "memory")
#define MBARRIER_WAIT_PARITY(mbar, parity) do { \
    asm volatile( \
        "{\n\t.reg .pred P1;\n" \
        "WAIT_LOOP_%=:\n\t" \
        "mbarrier.try_wait.parity.acquire.cta.shared::cta.b64 P1, [%0], %1, 0x989680;\n\t" \
        "@P1 bra.uni WAIT_DONE_%=;\n\t" \
        "bra.uni WAIT_LOOP_%=;\n\t" \
        "WAIT_DONE_%=:\n\t}" \
        :: "r"((uint32_t)(mbar)), "r"((uint32_t)(parity)) : "memory"); \
} while(0)

#define TCGEN05_ALLOC(smem_res, nCols) \
    asm volatile("tcgen05.alloc.cta_group::1.sync.aligned.shared::cta.b32 [%0], %1;" \
                 :: "r"((uint32_t)(smem_res)), "r"((uint32_t)(nCols)) : "memory")
#define TCGEN05_DEALLOC(tmem, nCols) \
    asm volatile("tcgen05.dealloc.cta_group::1.sync.aligned.b32 %0, %1;" :: "r"(tmem), "r"(nCols))
#define TCGEN05_RELINQUISH_ALLOC_PERMIT() \
    asm volatile("tcgen05.relinquish_alloc_permit.cta_group::1.sync.aligned;")
#define TCGEN05_COMMIT(mbar) \
    asm volatile("tcgen05.commit.cta_group::1.mbarrier::arrive::one.shared::cluster.b64 [%0];" \
                 :: "r"((uint32_t)(mbar)) : "memory")
#define TCGEN05_FENCE_BEFORE() asm volatile("tcgen05.fence::before_thread_sync;" ::: "memory")
#define TCGEN05_FENCE_AFTER()  asm volatile("tcgen05.fence::after_thread_sync;" ::: "memory")
#define TCGEN05_WAIT_LD()      asm volatile("tcgen05.wait::ld.sync.aligned;" ::: "memory")
#define FENCE_PROXY_ASYNC_SHARED_CTA() \
    asm volatile("fence.proxy.async.shared::cta;" ::: "memory")

#define TCGEN05_LD_32X32B_X32(r, tmem_addr) \
    asm volatile( \
        "tcgen05.ld.sync.aligned.32x32b.x32.b32 " \
        "{%0, %1, %2, %3, %4, %5, %6, %7, " \
        " %8, %9, %10, %11, %12, %13, %14, %15, " \
        " %16, %17, %18, %19, %20, %21, %22, %23, " \
        " %24, %25, %26, %27, %28, %29, %30, %31}, [%32];" \
        : "=r"((r)[0]),  "=r"((r)[1]),  "=r"((r)[2]),  "=r"((r)[3]), \
          "=r"((r)[4]),  "=r"((r)[5]),  "=r"((r)[6]),  "=r"((r)[7]), \
          "=r"((r)[8]),  "=r"((r)[9]),  "=r"((r)[10]), "=r"((r)[11]), \
          "=r"((r)[12]), "=r"((r)[13]), "=r"((r)[14]), "=r"((r)[15]), \
          "=r"((r)[16]), "=r"((r)[17]), "=r"((r)[18]), "=r"((r)[19]), \
          "=r"((r)[20]), "=r"((r)[21]), "=r"((r)[22]), "=r"((r)[23]), \
          "=r"((r)[24]), "=r"((r)[25]), "=r"((r)[26]), "=r"((r)[27]), \
          "=r"((r)[28]), "=r"((r)[29]), "=r"((r)[30]), "=r"((r)[31]) \
        : "r"(tmem_addr))

#define TCGEN05_MMA_F16_SS(d_tmem, a_desc, b_desc, idesc, enable_d) do { \
    uint32_t _en = (enable_d); \
    asm volatile( \
        "{\n\t.reg .pred p;\n\t" \
        "setp.ne.u32 p, %5, 0;\n\t" \
        "tcgen05.mma.cta_group::1.kind::f16 [%0], %1, %2, %3, {%4, %4, %4, %4}, p;\n\t" \
        "}" \
        :: "r"(d_tmem), "l"(a_desc), "l"(b_desc), "r"(idesc), "r"(0u), "r"(_en) \
        : "memory"); \
} while(0)

// SW128 K-major descriptor: layout=2, version=1, SBO=64, LBO=1
static constexpr uint64_t SMEM_DESC_BASE_SW128 =
    (uint64_t(2) << 61) | (uint64_t(1) << 46) | (uint64_t(64) << 32) | (uint64_t(1) << 16);
#define MAKE_SMEM_DESC(base_addr) \
    (SMEM_DESC_BASE_SW128 | ((uint64_t)((base_addr) >> 4) & 0x3FFF))

// idesc kind::f16: F32 accum (bit4), BF16 a (bit7), BF16 b (bit10), N/8@17, M/16@24
static constexpr uint32_t MMA_IDESC =
    (1u << 4) | (1u << 7) | (1u << 10) | ((256u / 8) << 17) | ((128u / 16) << 24);

// ---------------------------------------------------------------------------
// Kernel A: offset+mask 3x3 conv (unchanged, proven)
// ---------------------------------------------------------------------------
__global__ void conv_offmask_part(const float* __restrict__ x,
                                  const float* __restrict__ w_off,
                                  const float* __restrict__ w_mod) {
    __shared__ float xs[18][18];
    __shared__ float ws[27 * 9];

    const int tile  = blockIdx.x;
    const int chunk = blockIdx.y;
    const int b     = blockIdx.z;
    const int tileY = tile >> 2, tileX = tile & 3;
    const int ty0 = tileY * 16 - 1, tx0 = tileX * 16 - 1;
    const int tid = threadIdx.x;
    const int ly = tid >> 4, lx = tid & 15;

    float acc[27];
#pragma unroll
    for (int i = 0; i < 27; i++) acc[i] = 0.f;

    for (int cc = 0; cc < 64; cc++) {
        const int c = chunk * 64 + cc;
        for (int i = tid; i < 324; i += 256) {
            const int r = i / 18, q = i - r * 18;
            const int gy = ty0 + r, gx = tx0 + q;
            float v = 0.f;
            if (gy >= 0 && gy < H_ && gx >= 0 && gx < W_)
                v = x[(((b << 8) + c) << 12) + (gy << 6) + gx];
            xs[r][q] = v;
        }
        if (tid < 243) {
            const int co = tid / 9, tap = tid - co * 9;
            ws[tid] = (co < 18) ? w_off[(co * C_ + c) * 9 + tap]
                                : w_mod[((co - 18) * C_ + c) * 9 + tap];
        }
        __syncthreads();

        float xv[9];
#pragma unroll
        for (int t9 = 0; t9 < 9; t9++) {
            const int ky = t9 / 3, kx = t9 - ky * 3;
            xv[t9] = xs[ly + ky][lx + kx];
        }
#pragma unroll
        for (int co = 0; co < 27; co++) {
            float s = acc[co];
#pragma unroll
            for (int t9 = 0; t9 < 9; t9++)
                s = fmaf(ws[co * 9 + t9], xv[t9], s);
            acc[co] = s;
        }
        __syncthreads();
    }

    const int p = ((tileY * 16 + ly) << 6) + tileX * 16 + lx;
#pragma unroll
    for (int co = 0; co < 27; co++)
        g_part[(((chunk * 4 + b) * 27 + co) << 12) + p] = acc[co];
}

__global__ void offmask_finish(const float* __restrict__ b_off,
                               const float* __restrict__ b_mod) {
    const int idx = blockIdx.x * 256 + threadIdx.x;
    const int b  = idx / (27 * HW_);
    const int r  = idx - b * 27 * HW_;
    const int co = r >> 12;
    const int p  = r & 4095;

    float s = 0.f;
#pragma unroll
    for (int ch = 0; ch < 4; ch++)
        s += g_part[(((ch * 4 + b) * 27 + co) << 12) + p];

    if (co < 18) {
        s += b_off[co];
        g_off[((b * 18 + co) << 12) + p] = s;
    } else {
        s += b_mod[co - 18];
        g_mask[((b * 9 + (co - 18)) << 12) + p] = 2.f / (1.f + expf(-s));
    }
}

// ---------------------------------------------------------------------------
// Kernel T: transpose x -> xT[b][pix][c]
// ---------------------------------------------------------------------------
__global__ void transpose_x(const float* __restrict__ x) {
    __shared__ float ts[32][33];
    const int pt = blockIdx.x, ct = blockIdx.y, b = blockIdx.z;
    const int tx = threadIdx.x & 31, ty = threadIdx.x >> 5;
    const int c0 = ct << 5, p0 = pt << 5;
    const float* xb = x + (((size_t)b * C_) << 12);
#pragma unroll
    for (int i = 0; i < 4; i++)
        ts[ty + 8 * i][tx] = xb[((size_t)(c0 + ty + 8 * i) << 12) + p0 + tx];
    __syncthreads();
    float* xo = g_xT + (((size_t)b << 12) << 8);
#pragma unroll
    for (int i = 0; i < 4; i++)
        xo[((size_t)(p0 + ty + 8 * i) << 8) + c0 + tx] = ts[tx][ty + 8 * i];
}

// ---------------------------------------------------------------------------
// Kernel W: reorder + split w_reg -> g_wh/g_wl [o][k*256+c]
// ---------------------------------------------------------------------------
__global__ void wsplit(const float* __restrict__ w_reg) {
    const int idx = blockIdx.x * 256 + threadIdx.x;
    const int o = idx / CK_;
    const int r = idx - o * CK_;
    const int k = r >> 8;
    const int c = r & 255;
    const float v = w_reg[(o * C_ + c) * 9 + k];
    const __nv_bfloat16 h = __float2bfloat16(v);
    g_wh[idx] = h;
    g_wl[idx] = __float2bfloat16(v - __bfloat162float(h));
}

// ---------------------------------------------------------------------------
// Kernel B: deformable bilinear im2col -> split bf16, [b][p][k*256+c]
// ---------------------------------------------------------------------------
__global__ void dcn_im2col_bf16() {
    const int gw   = blockIdx.x * 8 + (threadIdx.x >> 5);
    const int lane = threadIdx.x & 31;
    const int p  = gw & 4095;
    const int bk = gw >> 12;
    const int b = bk / 9, k = bk - b * 9;
    const int h = p >> 6, w = p & 63;
    const int ky = k / 3, kx = k - ky * 3;

    const float dy = g_off[((b * 18 + 2 * k) << 12) + p];
    const float dx = g_off[((b * 18 + 2 * k + 1) << 12) + p];
    const float m  = g_mask[((b * 9 + k) << 12) + p];

    const float py = (float)(ky + h - 1) + dy;
    const float px = (float)(kx + w - 1) + dx;
    const float y0f = floorf(py), x0f = floorf(px);
    const float wy = py - y0f, wx = px - x0f;
    const int y0 = (int)y0f, x0 = (int)x0f;
    const int y1 = y0 + 1,  x1 = x0 + 1;

    const float fy0 = (y0 >= 0 && y0 < H_) ? 1.f : 0.f;
    const float fy1 = (y1 >= 0 && y1 < H_) ? 1.f : 0.f;
    const float fx0 = (x0 >= 0 && x0 < W_) ? 1.f : 0.f;
    const float fx1 = (x1 >= 0 && x1 < W_) ? 1.f : 0.f;

    const int y0c = min(max(y0, 0), H_ - 1), y1c = min(max(y1, 0), H_ - 1);
    const int x0c = min(max(x0, 0), W_ - 1), x1c = min(max(x1, 0), W_ - 1);

    const float w00 = (1.f - wy) * (1.f - wx) * fy0 * fx0 * m;
    const float w01 = (1.f - wy) * wx          * fy0 * fx1 * m;
    const float w10 = wy          * (1.f - wx) * fy1 * fx0 * m;
    const float w11 = wy          * wx          * fy1 * fx1 * m;

    const int i00 = (y0c << 6) + x0c, i01 = (y0c << 6) + x1c;
    const int i10 = (y1c << 6) + x0c, i11 = (y1c << 6) + x1c;

    const float* xr = g_xT + (((size_t)b << 12) << 8);
    const int co = lane << 3;

    const float4* q00 = (const float4*)(xr + ((size_t)i00 << 8) + co);
    const float4* q01 = (const float4*)(xr + ((size_t)i01 << 8) + co);
    const float4* q10 = (const float4*)(xr + ((size_t)i10 << 8) + co);
    const float4* q11 = (const float4*)(xr + ((size_t)i11 << 8) + co);

    float v[8];
#pragma unroll
    for (int half = 0; half < 2; half++) {
        const float4 a = q00[half], bb = q01[half], cc = q10[half], dd = q11[half];
        v[half*4+0] = w00*a.x + w01*bb.x + w10*cc.x + w11*dd.x;
        v[half*4+1] = w00*a.y + w01*bb.y + w10*cc.y + w11*dd.y;
        v[half*4+2] = w00*a.z + w01*bb.z + w10*cc.z + w11*dd.z;
        v[half*4+3] = w00*a.w + w01*bb.w + w10*cc.w + w11*dd.w;
    }

    __align__(16) __nv_bfloat16 hh[8];
    __align__(16) __nv_bfloat16 ll[8];
#pragma unroll
    for (int i = 0; i < 8; i++) {
        hh[i] = __float2bfloat16(v[i]);
        ll[i] = __float2bfloat16(v[i] - __bfloat162float(hh[i]));
    }
    const size_t ob = ((size_t)(b * HW_ + p)) * CK_ + k * 256 + co;
    *reinterpret_cast<uint4*>(&g_colh[ob]) = *reinterpret_cast<const uint4*>(hh);
    *reinterpret_cast<uint4*>(&g_coll[ob]) = *reinterpret_cast<const uint4*>(ll);
}

// ---------------------------------------------------------------------------
// Kernel C: tensor GEMM. Per CTA: D[128 pos, 256 out], K=2304.
// Split-bf16 (hh + hl + lh). Double-buffered cp.async stages (K-chunk 64).
// Arch path: tcgen05 when available, else mma.sync (HMMA) fallback.
// ---------------------------------------------------------------------------
#define SM_TPTR 0
#define SM_MBAR 8
#define SM_INV  64
#define SM_SH   1088
#define SM_STG  4096
#define STG_SZ  98304
#define OFF_AH  0
#define OFF_AL  16384
#define OFF_BH  32768
#define OFF_BL  65536
#define GEMM_SMEM (SM_STG + 2 * STG_SZ)   // 200704 bytes

__device__ __forceinline__ void fill_stage(uint32_t stg,
                                           const __nv_bfloat16* __restrict__ Ah,
                                           const __nv_bfloat16* __restrict__ Al,
                                           int k0, int tid) {
#pragma unroll
    for (int i = 0; i < 4; i++) {
        const int ci = i * 256 + tid;
        const int row = ci >> 3, c16 = ci & 7;
        const uint32_t so = SMEM_SWIZZLE_128B((uint32_t)(row * 128 + c16 * 16));
        const size_t go = (size_t)row * CK_ + k0 + c16 * 8;
        CPA16(stg + OFF_AH + so, Ah + go);
        CPA16(stg + OFF_AL + so, Al + go);
    }
#pragma unroll
    for (int i = 0; i < 8; i++) {
        const int ci = i * 256 + tid;
        const int row = ci >> 3, c16 = ci & 7;
        const uint32_t so = SMEM_SWIZZLE_128B((uint32_t)(row * 128 + c16 * 16));
        const size_t go = (size_t)row * CK_ + k0 + c16 * 8;
        CPA16(stg + OFF_BH + so, g_wh + go);
        CPA16(stg + OFF_BL + so, g_wl + go);
    }
}

__global__ __launch_bounds__(256, 1)
void dcn_gemm_tc(const float* __restrict__ gamma, const float* __restrict__ beta,
                 const float* __restrict__ rmean, const float* __restrict__ rvar,
                 float* __restrict__ out) {
    extern __shared__ char smem[];
    const uint32_t sb = smem_to_u32(smem);
    const int tid = threadIdx.x;
    const int wid = tid >> 5, lane = tid & 31;
    const int bx = blockIdx.x;
    const int b  = bx >> 5;
    const int p0 = (bx & 31) << 7;

    // BN params -> smem
    {
        const float iv = gamma[tid] * rsqrtf(rvar[tid] + BN_EPS);
        reinterpret_cast<float*>(smem + SM_INV)[tid] = iv;
        reinterpret_cast<float*>(smem + SM_SH)[tid]  = beta[tid] - rmean[tid] * iv;
    }

    const __nv_bfloat16* Ah = g_colh + (size_t)(b * HW_ + p0) * CK_;
    const __nv_bfloat16* Al = g_coll + (size_t)(b * HW_ + p0) * CK_;
    const int NKT = CK_ / 64;   // 36

#if HAS_TCGEN05
    // ======================== tcgen05 path =================================
    if (wid == 0) { TCGEN05_ALLOC(sb + SM_TPTR, 256); }
    if (tid == 0) { MBARRIER_INIT(sb + SM_MBAR, 1); MBARRIER_INIT(sb + SM_MBAR + 8, 1); }
    __syncthreads();
    uint32_t tmem;
    asm volatile("ld.shared.b32 %0, [%1];" : "=r"(tmem) : "r"(sb + SM_TPTR));

    int wcnt0 = 0, wcnt1 = 0;
    for (int kt = 0; kt < NKT; kt++) {
        const int buf = kt & 1;
        const uint32_t stg = sb + SM_STG + buf * STG_SZ;
        if (kt >= 2) {
            if (buf == 0) { MBARRIER_WAIT_PARITY(sb + SM_MBAR,     (uint32_t)(wcnt0 & 1)); wcnt0++; }
            else          { MBARRIER_WAIT_PARITY(sb + SM_MBAR + 8, (uint32_t)(wcnt1 & 1)); wcnt1++; }
        }
        fill_stage(stg, Ah, Al, kt * 64, tid);
        CPA_COMMIT();
        CPA_WAIT(0);
        __syncthreads();
        if (wid == 0) {
            FENCE_PROXY_ASYNC_SHARED_CTA();
            if (elect_one_pred()) {
                const uint64_t adh = MAKE_SMEM_DESC(stg + OFF_AH);
                const uint64_t adl = MAKE_SMEM_DESC(stg + OFF_AL);
                const uint64_t bdh = MAKE_SMEM_DESC(stg + OFF_BH);
                const uint64_t bdl = MAKE_SMEM_DESC(stg + OFF_BL);
#pragma unroll
                for (int s = 0; s < 4; s++) {
                    const uint32_t en = (kt > 0 || s > 0) ? 1u : 0u;
                    TCGEN05_MMA_F16_SS(tmem, adh + 2 * s, bdh + 2 * s, MMA_IDESC, en);
                    TCGEN05_MMA_F16_SS(tmem, adh + 2 * s, bdl + 2 * s, MMA_IDESC, 1u);
                    TCGEN05_MMA_F16_SS(tmem, adl + 2 * s, bdh + 2 * s, MMA_IDESC, 1u);
                }
                TCGEN05_COMMIT(sb + SM_MBAR + 8 * buf);
            }
        }
    }
    MBARRIER_WAIT_PARITY(sb + SM_MBAR,     (uint32_t)(wcnt0 & 1));
    MBARRIER_WAIT_PARITY(sb + SM_MBAR + 8, (uint32_t)(wcnt1 & 1));
    TCGEN05_FENCE_AFTER();

    {
        const int sub = wid & 3, cgrp = wid >> 2;
        const int prow = p0 + sub * 32 + lane;
        float* ob = out + (((size_t)b * CO_) << 12) + prow;
        const float* inv = reinterpret_cast<const float*>(smem + SM_INV);
        const float* shf = reinterpret_cast<const float*>(smem + SM_SH);
#pragma unroll
        for (int ch = 0; ch < 4; ch++) {
            const int cbase = cgrp * 128 + ch * 32;
            uint32_t r[32];
            TCGEN05_LD_32X32B_X32(r, tmem + (uint32_t)cbase);
            TCGEN05_WAIT_LD();
#pragma unroll
            for (int j = 0; j < 32; j++) {
                const int o = cbase + j;
                float v = __uint_as_float(r[j]);
                v = fmaxf(fmaf(v, inv[o], shf[o]), 0.f);
                ob[(size_t)o << 12] = v;
            }
        }
    }
    TCGEN05_FENCE_BEFORE();
    __syncthreads();
    if (tid == 0) { MBARRIER_INVAL(sb + SM_MBAR); MBARRIER_INVAL(sb + SM_MBAR + 8); }
    __syncthreads();
    if (wid == 0) { TCGEN05_RELINQUISH_ALLOC_PERMIT(); TCGEN05_DEALLOC(tmem, 256); }

#else
    // ===================== mma.sync (HMMA) fallback =========================
    // 8 warps: warp tile 64(M) x 64(N). wm = (wid&1)*64, wn = (wid>>1)*64.
    __syncthreads();   // BN smem visible

    float acc[4][8][4];
#pragma unroll
    for (int mb = 0; mb < 4; mb++)
#pragma unroll
        for (int nb = 0; nb < 8; nb++)
#pragma unroll
            for (int j = 0; j < 4; j++) acc[mb][nb][j] = 0.f;

    const int wm = (wid & 1) << 6;
    const int wn = (wid >> 1) << 6;

    fill_stage(sb + SM_STG, Ah, Al, 0, tid);
    CPA_COMMIT();

    for (int kt = 0; kt < NKT; kt++) {
        const uint32_t stg = sb + SM_STG + (uint32_t)(kt & 1) * STG_SZ;
        if (kt + 1 < NKT) {
            fill_stage(sb + SM_STG + (uint32_t)((kt + 1) & 1) * STG_SZ, Ah, Al, (kt + 1) * 64, tid);
            CPA_COMMIT();
            CPA_WAIT(1);
        } else {
            CPA_WAIT(0);
        }
        __syncthreads();

#pragma unroll
        for (int ks = 0; ks < 4; ks++) {
            uint32_t ahf[4][4], alf[4][4], bf[8][2];
            const uint32_t kbA = (uint32_t)(ks * 32) + ((lane & 16) ? 16u : 0u);
            const int rA = wm + (lane & 15);
#pragma unroll
            for (int mb = 0; mb < 4; mb++) {
                const uint32_t off = SMEM_SWIZZLE_128B((uint32_t)((rA + mb * 16) * 128) + kbA);
                LDSM_X4(ahf[mb][0], ahf[mb][1], ahf[mb][2], ahf[mb][3], stg + OFF_AH + off);
                LDSM_X4(alf[mb][0], alf[mb][1], alf[mb][2], alf[mb][3], stg + OFF_AL + off);
            }
            const uint32_t kbB = (uint32_t)(ks * 32) + (uint32_t)((lane & 8) << 1);
            const int rB = wn + (lane & 7) + ((lane & 16) >> 1);
#pragma unroll
            for (int q = 0; q < 4; q++) {
                const uint32_t off = SMEM_SWIZZLE_128B((uint32_t)((rB + q * 16) * 128) + kbB);
                LDSM_X4(bf[2*q][0], bf[2*q][1], bf[2*q+1][0], bf[2*q+1][1], stg + OFF_BH + off);
            }
#pragma unroll
            for (int mb = 0; mb < 4; mb++)
#pragma unroll
                for (int nb = 0; nb < 8; nb++) {
                    MMA16816(acc[mb][nb], ahf[mb], bf[nb][0], bf[nb][1]);
                    MMA16816(acc[mb][nb], alf[mb], bf[nb][0], bf[nb][1]);
                }
            // reload B-lo over bf, multiply with A-hi
#pragma unroll
            for (int q = 0; q < 4; q++) {
                const uint32_t off = SMEM_SWIZZLE_128B((uint32_t)((rB + q * 16) * 128) + kbB);
                LDSM_X4(bf[2*q][0], bf[2*q][1], bf[2*q+1][0], bf[2*q+1][1], stg + OFF_BL + off);
            }
#pragma unroll
            for (int mb = 0; mb < 4; mb++)
#pragma unroll
                for (int nb = 0; nb < 8; nb++)
                    MMA16816(acc[mb][nb], ahf[mb], bf[nb][0], bf[nb][1]);
        }
        __syncthreads();
    }

    // Epilogue: BN + ReLU, direct stores.
    {
        const int g = lane >> 2, t = lane & 3;
        const float* inv = reinterpret_cast<const float*>(smem + SM_INV);
        const float* shf = reinterpret_cast<const float*>(smem + SM_SH);
        float* outb = out + (((size_t)b * CO_) << 12);
#pragma unroll
        for (int mb = 0; mb < 4; mb++) {
            const int p = p0 + wm + mb * 16 + g;
#pragma unroll
            for (int nb = 0; nb < 8; nb++) {
                const int o = wn + nb * 8 + 2 * t;
                const float i0 = inv[o],     s0 = shf[o];
                const float i1 = inv[o + 1], s1 = shf[o + 1];
                float* c0p = outb + ((size_t)o << 12);
                float* c1p = c0p + 4096;
                c0p[p]     = fmaxf(fmaf(acc[mb][nb][0], i0, s0), 0.f);
                c1p[p]     = fmaxf(fmaf(acc[mb][nb][1], i1, s1), 0.f);
                c0p[p + 8] = fmaxf(fmaf(acc[mb][nb][2], i0, s0), 0.f);
                c1p[p + 8] = fmaxf(fmaf(acc[mb][nb][3], i1, s1), 0.f);
            }
        }
    }
#endif
}

// ---------------------------------------------------------------------------
// Launch
// ---------------------------------------------------------------------------
extern "C" void kernel_launch(void* const* d_in, const int* in_sizes, int n_in,
                              void* d_out, int out_size) {
    const float* x     = (const float*)d_in[0];
    const float* w_off = (const float*)d_in[1];
    const float* b_off = (const float*)d_in[2];
    const float* w_mod = (const float*)d_in[3];
    const float* b_mod = (const float*)d_in[4];
    const float* w_reg = (const float*)d_in[5];
    const float* gamma = (const float*)d_in[6];
    const float* beta  = (const float*)d_in[7];
    const float* rmean = (const float*)d_in[8];
    const float* rvar  = (const float*)d_in[9];
    float* out = (float*)d_out;

    cudaFuncSetAttribute(dcn_gemm_tc, cudaFuncAttributeMaxDynamicSharedMemorySize, GEMM_SMEM);

    // 1) offset + mask conv
    conv_offmask_part<<<dim3(16, 4, 4), 256>>>(x, w_off, w_mod);
    offmask_finish<<<(B_ * 27 * HW_) / 256, 256>>>(b_off, b_mod);

    // 2) transpose x, split weights
    transpose_x<<<dim3(128, 8, 4), 256>>>(x);
    wsplit<<<(CO_ * CK_) / 256, 256>>>(w_reg);

    // 3) deformable im2col -> split bf16 columns
    dcn_im2col_bf16<<<(B_ * K_ * HW_) / 8, 256>>>();

    // 4) tensor GEMM + BN + ReLU
    dcn_gemm_tc<<<128, 256, GEMM_SMEM>>>(gamma, beta, rmean, rvar, out);
}

// round 14
// speedup vs baseline: 1.1505x; 1.1505x over previous
#include <cuda_runtime.h>
#include <cuda_fp16.h>
#include <cstdint>
#include <math.h>

// ---------------------------------------------------------------------------
// Problem constants
// ---------------------------------------------------------------------------
#define B_  4
#define C_  256
#define CO_ 256
#define H_  64
#define W_  64
#define HW_ 4096
#define K_  9
#define CK_ 2304
#define BN_EPS 1e-5f
#define NCHUNK 16

// ---------------------------------------------------------------------------
// Device scratch (module-scope globals: allocation-free per harness rules)
// ---------------------------------------------------------------------------
__device__ float g_part[NCHUNK * B_ * 27 * HW_];
__device__ float g_off [B_ * 18 * HW_];
__device__ float g_mask[B_ * 9 * HW_];
__device__ __align__(256) float g_xT[(size_t)B_ * HW_ * C_];          // x transposed [b][pix][c]
__device__ __align__(256) __half g_col[(size_t)B_ * HW_ * CK_];       // col fp16 [b][p][k*256+c]
__device__ __align__(256) __half g_wh[CO_ * CK_];                     // w hi  [o][k*256+c]
__device__ __align__(256) __half g_wl[CO_ * CK_];                     // w lo

// ---------------------------------------------------------------------------
// Portable PTX helpers (sm_80+: cp.async, ldmatrix, mma.sync)
// ---------------------------------------------------------------------------
__device__ __forceinline__ uint32_t smem_to_u32(const void* smem_ptr) {
    uint32_t addr;
    asm("{ .reg .u64 tmp; cvta.to.shared.u64 tmp, %1; cvt.u32.u64 %0, tmp; }"
        : "=r"(addr) : "l"(smem_ptr));
    return addr;
}

#define CPA16(dst, src) \
    asm volatile("cp.async.cg.shared.global [%0], [%1], 16;" \
                 :: "r"((uint32_t)(dst)), "l"(src))
#define CPA_COMMIT()    asm volatile("cp.async.commit_group;" ::: "memory")
#define CPA_WAIT(n)     asm volatile("cp.async.wait_group %0;" :: "n"(n) : "memory")

#define SMEM_SWIZZLE_128B(byte_offset) \
    ((byte_offset) ^ (((byte_offset) >> 3) & 0x70))

#define LDSM_X4(r0, r1, r2, r3, addr) \
    asm volatile("ldmatrix.sync.aligned.m8n8.x4.shared.b16 {%0, %1, %2, %3}, [%4];" \
        : "=r"(r0), "=r"(r1), "=r"(r2), "=r"(r3) : "r"(addr))

#define MMA16816F16(c, a, b0, b1) \
    asm volatile("mma.sync.aligned.m16n8k16.row.col.f32.f16.f16.f32 " \
        "{%0, %1, %2, %3}, {%4, %5, %6, %7}, {%8, %9}, {%0, %1, %2, %3};" \
        : "+f"((c)[0]), "+f"((c)[1]), "+f"((c)[2]), "+f"((c)[3]) \
        : "r"((a)[0]), "r"((a)[1]), "r"((a)[2]), "r"((a)[3]), "r"(b0), "r"(b1))

// ---------------------------------------------------------------------------
// Kernel A: offset+mask 3x3 conv, 16-way channel-chunked partials.
// grid (16 tiles, NCHUNK chunks, B), 256 threads = 16x16 pixel tile.
// ---------------------------------------------------------------------------
__global__ void conv_offmask_part(const float* __restrict__ x,
                                  const float* __restrict__ w_off,
                                  const float* __restrict__ w_mod) {
    __shared__ float xs[18][18];
    __shared__ float ws[27 * 9];

    const int tile  = blockIdx.x;
    const int chunk = blockIdx.y;
    const int b     = blockIdx.z;
    const int tileY = tile >> 2, tileX = tile & 3;
    const int ty0 = tileY * 16 - 1, tx0 = tileX * 16 - 1;
    const int tid = threadIdx.x;
    const int ly = tid >> 4, lx = tid & 15;

    float acc[27];
#pragma unroll
    for (int i = 0; i < 27; i++) acc[i] = 0.f;

    const int CPC = C_ / NCHUNK;   // 16 channels per chunk
    for (int cc = 0; cc < CPC; cc++) {
        const int c = chunk * CPC + cc;
        for (int i = tid; i < 324; i += 256) {
            const int r = i / 18, q = i - r * 18;
            const int gy = ty0 + r, gx = tx0 + q;
            float v = 0.f;
            if (gy >= 0 && gy < H_ && gx >= 0 && gx < W_)
                v = x[(((b << 8) + c) << 12) + (gy << 6) + gx];
            xs[r][q] = v;
        }
        if (tid < 243) {
            const int co = tid / 9, tap = tid - co * 9;
            ws[tid] = (co < 18) ? w_off[(co * C_ + c) * 9 + tap]
                                : w_mod[((co - 18) * C_ + c) * 9 + tap];
        }
        __syncthreads();

        float xv[9];
#pragma unroll
        for (int t9 = 0; t9 < 9; t9++) {
            const int ky = t9 / 3, kx = t9 - ky * 3;
            xv[t9] = xs[ly + ky][lx + kx];
        }
#pragma unroll
        for (int co = 0; co < 27; co++) {
            float s = acc[co];
#pragma unroll
            for (int t9 = 0; t9 < 9; t9++)
                s = fmaf(ws[co * 9 + t9], xv[t9], s);
            acc[co] = s;
        }
        __syncthreads();
    }

    const int p = ((tileY * 16 + ly) << 6) + tileX * 16 + lx;
#pragma unroll
    for (int co = 0; co < 27; co++)
        g_part[(((chunk * 4 + b) * 27 + co) << 12) + p] = acc[co];
}

__global__ void offmask_finish(const float* __restrict__ b_off,
                               const float* __restrict__ b_mod) {
    const int idx = blockIdx.x * 256 + threadIdx.x;
    const int b  = idx / (27 * HW_);
    const int r  = idx - b * 27 * HW_;
    const int co = r >> 12;
    const int p  = r & 4095;

    float s = 0.f;
#pragma unroll
    for (int ch = 0; ch < NCHUNK; ch++)
        s += g_part[(((ch * 4 + b) * 27 + co) << 12) + p];

    if (co < 18) {
        s += b_off[co];
        g_off[((b * 18 + co) << 12) + p] = s;
    } else {
        s += b_mod[co - 18];
        g_mask[((b * 9 + (co - 18)) << 12) + p] = 2.f / (1.f + expf(-s));
    }
}

// ---------------------------------------------------------------------------
// Kernel T: transpose x -> xT[b][pix][c]
// ---------------------------------------------------------------------------
__global__ void transpose_x(const float* __restrict__ x) {
    __shared__ float ts[32][33];
    const int pt = blockIdx.x, ct = blockIdx.y, b = blockIdx.z;
    const int tx = threadIdx.x & 31, ty = threadIdx.x >> 5;
    const int c0 = ct << 5, p0 = pt << 5;
    const float* xb = x + (((size_t)b * C_) << 12);
#pragma unroll
    for (int i = 0; i < 4; i++)
        ts[ty + 8 * i][tx] = xb[((size_t)(c0 + ty + 8 * i) << 12) + p0 + tx];
    __syncthreads();
    float* xo = g_xT + (((size_t)b << 12) << 8);
#pragma unroll
    for (int i = 0; i < 4; i++)
        xo[((size_t)(p0 + ty + 8 * i) << 8) + c0 + tx] = ts[tx][ty + 8 * i];
}

// ---------------------------------------------------------------------------
// Kernel W: reorder + split w_reg -> g_wh/g_wl [o][k*256+c] (fp16 hi/lo)
// ---------------------------------------------------------------------------
__global__ void wsplit(const float* __restrict__ w_reg) {
    const int idx = blockIdx.x * 256 + threadIdx.x;
    const int o = idx / CK_;
    const int r = idx - o * CK_;
    const int k = r >> 8;
    const int c = r & 255;
    const float v = w_reg[(o * C_ + c) * 9 + k];
    const __half h = __float2half(v);
    g_wh[idx] = h;
    g_wl[idx] = __float2half(v - __half2float(h));
}

// ---------------------------------------------------------------------------
// Kernel B: deformable bilinear im2col -> fp16, [b][p][k*256+c]
// One warp per (b,k,p); lanes cover 8 channels each -> fully coalesced.
// ---------------------------------------------------------------------------
__global__ void dcn_im2col_f16() {
    const int gw   = blockIdx.x * 8 + (threadIdx.x >> 5);
    const int lane = threadIdx.x & 31;
    const int p  = gw & 4095;
    const int bk = gw >> 12;
    const int b = bk / 9, k = bk - b * 9;
    const int h = p >> 6, w = p & 63;
    const int ky = k / 3, kx = k - ky * 3;

    const float dy = g_off[((b * 18 + 2 * k) << 12) + p];
    const float dx = g_off[((b * 18 + 2 * k + 1) << 12) + p];
    const float m  = g_mask[((b * 9 + k) << 12) + p];

    const float py = (float)(ky + h - 1) + dy;
    const float px = (float)(kx + w - 1) + dx;
    const float y0f = floorf(py), x0f = floorf(px);
    const float wy = py - y0f, wx = px - x0f;
    const int y0 = (int)y0f, x0 = (int)x0f;
    const int y1 = y0 + 1,  x1 = x0 + 1;

    const float fy0 = (y0 >= 0 && y0 < H_) ? 1.f : 0.f;
    const float fy1 = (y1 >= 0 && y1 < H_) ? 1.f : 0.f;
    const float fx0 = (x0 >= 0 && x0 < W_) ? 1.f : 0.f;
    const float fx1 = (x1 >= 0 && x1 < W_) ? 1.f : 0.f;

    const int y0c = min(max(y0, 0), H_ - 1), y1c = min(max(y1, 0), H_ - 1);
    const int x0c = min(max(x0, 0), W_ - 1), x1c = min(max(x1, 0), W_ - 1);

    const float w00 = (1.f - wy) * (1.f - wx) * fy0 * fx0 * m;
    const float w01 = (1.f - wy) * wx          * fy0 * fx1 * m;
    const float w10 = wy          * (1.f - wx) * fy1 * fx0 * m;
    const float w11 = wy          * wx          * fy1 * fx1 * m;

    const int i00 = (y0c << 6) + x0c, i01 = (y0c << 6) + x1c;
    const int i10 = (y1c << 6) + x0c, i11 = (y1c << 6) + x1c;

    const float* xr = g_xT + (((size_t)b << 12) << 8);
    const int co = lane << 3;

    const float4* q00 = (const float4*)(xr + ((size_t)i00 << 8) + co);
    const float4* q01 = (const float4*)(xr + ((size_t)i01 << 8) + co);
    const float4* q10 = (const float4*)(xr + ((size_t)i10 << 8) + co);
    const float4* q11 = (const float4*)(xr + ((size_t)i11 << 8) + co);

    float v[8];
#pragma unroll
    for (int half = 0; half < 2; half++) {
        const float4 a = q00[half], bb = q01[half], cc = q10[half], dd = q11[half];
        v[half*4+0] = w00*a.x + w01*bb.x + w10*cc.x + w11*dd.x;
        v[half*4+1] = w00*a.y + w01*bb.y + w10*cc.y + w11*dd.y;
        v[half*4+2] = w00*a.z + w01*bb.z + w10*cc.z + w11*dd.z;
        v[half*4+3] = w00*a.w + w01*bb.w + w10*cc.w + w11*dd.w;
    }

    __align__(16) __half hh[8];
#pragma unroll
    for (int i = 0; i < 8; i++)
        hh[i] = __float2half(v[i]);

    const size_t ob = ((size_t)(b * HW_ + p)) * CK_ + k * 256 + co;
    *reinterpret_cast<uint4*>(&g_col[ob]) = *reinterpret_cast<const uint4*>(hh);
}

// ---------------------------------------------------------------------------
// Kernel C: mma.sync fp16 GEMM. Per CTA: D[128 pos, 256 out], K=2304.
// A single fp16, B split hi/lo -> 2 MMA terms. Double-buffered cp.async.
// ---------------------------------------------------------------------------
#define SM_INV  0
#define SM_SH   1024
#define SM_STG  2048
#define STG_SZ  81920            // 80 KB per stage: A 16K + Bh 32K + Bl 32K
#define OFF_A   0
#define OFF_BH  16384
#define OFF_BL  49152
#define GEMM_SMEM (SM_STG + 2 * STG_SZ)   // 165888 bytes

__device__ __forceinline__ void fill_stage(uint32_t stg,
                                           const __half* __restrict__ Ac,
                                           int k0, int tid) {
    // A: 128 rows x 128B (64 fp16)
#pragma unroll
    for (int i = 0; i < 4; i++) {
        const int ci = i * 256 + tid;
        const int row = ci >> 3, c16 = ci & 7;
        const uint32_t so = SMEM_SWIZZLE_128B((uint32_t)(row * 128 + c16 * 16));
        const size_t go = (size_t)row * CK_ + k0 + c16 * 8;
        CPA16(stg + OFF_A + so, Ac + go);
    }
    // B: 256 rows x 128B, hi + lo
#pragma unroll
    for (int i = 0; i < 8; i++) {
        const int ci = i * 256 + tid;
        const int row = ci >> 3, c16 = ci & 7;
        const uint32_t so = SMEM_SWIZZLE_128B((uint32_t)(row * 128 + c16 * 16));
        const size_t go = (size_t)row * CK_ + k0 + c16 * 8;
        CPA16(stg + OFF_BH + so, g_wh + go);
        CPA16(stg + OFF_BL + so, g_wl + go);
    }
}

__global__ __launch_bounds__(256, 1)
void dcn_gemm_tc(const float* __restrict__ gamma, const float* __restrict__ beta,
                 const float* __restrict__ rmean, const float* __restrict__ rvar,
                 float* __restrict__ out) {
    extern __shared__ char smem[];
    const uint32_t sb = smem_to_u32(smem);
    const int tid = threadIdx.x;
    const int wid = tid >> 5, lane = tid & 31;
    const int bx = blockIdx.x;
    const int b  = bx >> 5;
    const int p0 = (bx & 31) << 7;

    // BN params -> smem
    {
        const float iv = gamma[tid] * rsqrtf(rvar[tid] + BN_EPS);
        reinterpret_cast<float*>(smem + SM_INV)[tid] = iv;
        reinterpret_cast<float*>(smem + SM_SH)[tid]  = beta[tid] - rmean[tid] * iv;
    }
    __syncthreads();

    const __half* Ac = g_col + (size_t)(b * HW_ + p0) * CK_;
    const int NKT = CK_ / 64;   // 36

    float acc[4][8][4];
#pragma unroll
    for (int mb = 0; mb < 4; mb++)
#pragma unroll
        for (int nb = 0; nb < 8; nb++)
#pragma unroll
            for (int j = 0; j < 4; j++) acc[mb][nb][j] = 0.f;

    const int wm = (wid & 1) << 6;     // 0 or 64 (M)
    const int wn = (wid >> 1) << 6;    // 0..192 (N)

    fill_stage(sb + SM_STG, Ac, 0, tid);
    CPA_COMMIT();

    for (int kt = 0; kt < NKT; kt++) {
        const uint32_t stg = sb + SM_STG + (uint32_t)(kt & 1) * STG_SZ;
        if (kt + 1 < NKT) {
            fill_stage(sb + SM_STG + (uint32_t)((kt + 1) & 1) * STG_SZ, Ac, (kt + 1) * 64, tid);
            CPA_COMMIT();
            CPA_WAIT(1);
        } else {
            CPA_WAIT(0);
        }
        __syncthreads();

#pragma unroll
        for (int ks = 0; ks < 4; ks++) {
            uint32_t af[4][4], bh[8][2], bl[8][2];
            const uint32_t kbA = (uint32_t)(ks * 32) + ((lane & 16) ? 16u : 0u);
            const int rA = wm + (lane & 15);
#pragma unroll
            for (int mb = 0; mb < 4; mb++) {
                const uint32_t off = SMEM_SWIZZLE_128B((uint32_t)((rA + mb * 16) * 128) + kbA);
                LDSM_X4(af[mb][0], af[mb][1], af[mb][2], af[mb][3], stg + OFF_A + off);
            }
            const uint32_t kbB = (uint32_t)(ks * 32) + (uint32_t)((lane & 8) << 1);
            const int rB = wn + (lane & 7) + ((lane & 16) >> 1);
#pragma unroll
            for (int q = 0; q < 4; q++) {
                const uint32_t off = SMEM_SWIZZLE_128B((uint32_t)((rB + q * 16) * 128) + kbB);
                LDSM_X4(bh[2*q][0], bh[2*q][1], bh[2*q+1][0], bh[2*q+1][1], stg + OFF_BH + off);
            }
#pragma unroll
            for (int q = 0; q < 4; q++) {
                const uint32_t off = SMEM_SWIZZLE_128B((uint32_t)((rB + q * 16) * 128) + kbB);
                LDSM_X4(bl[2*q][0], bl[2*q][1], bl[2*q+1][0], bl[2*q+1][1], stg + OFF_BL + off);
            }
#pragma unroll
            for (int mb = 0; mb < 4; mb++)
#pragma unroll
                for (int nb = 0; nb < 8; nb++) {
                    MMA16816F16(acc[mb][nb], af[mb], bh[nb][0], bh[nb][1]);
                    MMA16816F16(acc[mb][nb], af[mb], bl[nb][0], bl[nb][1]);
                }
        }
        __syncthreads();
    }

    // Epilogue: BN + ReLU, direct stores.
    {
        const int g = lane >> 2, t = lane & 3;
        const float* inv = reinterpret_cast<const float*>(smem + SM_INV);
        const float* shf = reinterpret_cast<const float*>(smem + SM_SH);
        float* outb = out + (((size_t)b * CO_) << 12);
#pragma unroll
        for (int mb = 0; mb < 4; mb++) {
            const int p = p0 + wm + mb * 16 + g;
#pragma unroll
            for (int nb = 0; nb < 8; nb++) {
                const int o = wn + nb * 8 + 2 * t;
                const float i0 = inv[o],     s0 = shf[o];
                const float i1 = inv[o + 1], s1 = shf[o + 1];
                float* c0p = outb + ((size_t)o << 12);
                float* c1p = c0p + 4096;
                c0p[p]     = fmaxf(fmaf(acc[mb][nb][0], i0, s0), 0.f);
                c1p[p]     = fmaxf(fmaf(acc[mb][nb][1], i1, s1), 0.f);
                c0p[p + 8] = fmaxf(fmaf(acc[mb][nb][2], i0, s0), 0.f);
                c1p[p + 8] = fmaxf(fmaf(acc[mb][nb][3], i1, s1), 0.f);
            }
        }
    }
}

// ---------------------------------------------------------------------------
// Launch
// ---------------------------------------------------------------------------
extern "C" void kernel_launch(void* const* d_in, const int* in_sizes, int n_in,
                              void* d_out, int out_size) {
    const float* x     = (const float*)d_in[0];
    const float* w_off = (const float*)d_in[1];
    const float* b_off = (const float*)d_in[2];
    const float* w_mod = (const float*)d_in[3];
    const float* b_mod = (const float*)d_in[4];
    const float* w_reg = (const float*)d_in[5];
    const float* gamma = (const float*)d_in[6];
    const float* beta  = (const float*)d_in[7];
    const float* rmean = (const float*)d_in[8];
    const float* rvar  = (const float*)d_in[9];
    float* out = (float*)d_out;

    cudaFuncSetAttribute(dcn_gemm_tc, cudaFuncAttributeMaxDynamicSharedMemorySize, GEMM_SMEM);

    // 1) offset + mask conv (16-way chunked -> finish)
    conv_offmask_part<<<dim3(16, NCHUNK, 4), 256>>>(x, w_off, w_mod);
    offmask_finish<<<(B_ * 27 * HW_) / 256, 256>>>(b_off, b_mod);

    // 2) transpose x, split weights
    transpose_x<<<dim3(128, 8, 4), 256>>>(x);
    wsplit<<<(CO_ * CK_) / 256, 256>>>(w_reg);

    // 3) deformable im2col -> fp16 columns
    dcn_im2col_f16<<<(B_ * K_ * HW_) / 8, 256>>>();

    // 4) tensor GEMM + BN + ReLU
    dcn_gemm_tc<<<128, 256, GEMM_SMEM>>>(gamma, beta, rmean, rvar, out);
}